// round 12
// baseline (speedup 1.0000x reference)
#include <cuda_runtime.h>
#include <cuda_bf16.h>
#include <cuda_fp16.h>
#include <cstdint>

// ---------------------------------------------------------------------------
// Attention_71485435675049 — Round 11
// R10 + 4-stage cp.async multistage (ONE __syncthreads per K-chunk) in both
// gemm_f16 and attn_mma. Numerics identical to R10 (rel_err 6.5e-4).
// ---------------------------------------------------------------------------

#define ATT_SCALE 0.125f
#define LOG2E 1.4426950408889634f

// ------------------------- scratch (no allocs allowed) ----------------------
__device__ __half g_x16[8192 * 1024];
__device__ __half g_wqkvt16[3072 * 1024];    // [N,K] transposed fp16
__device__ __half g_woutt16[1024 * 1024];    // [N,K] transposed fp16
__device__ __half g_qkv16[8192 * 3072];
__device__ __half g_att16[8192 * 1024];

// ------------------------- PTX helpers -------------------------------------
__device__ __forceinline__ uint32_t smem_u32(const void* p) {
    uint32_t a;
    asm("{ .reg .u64 t; cvta.to.shared.u64 t, %1; cvt.u32.u64 %0, t; }"
        : "=r"(a) : "l"(p));
    return a;
}

__device__ __forceinline__ void cp_async16(uint32_t dst, const void* src) {
    asm volatile("cp.async.cg.shared.global [%0], [%1], 16;\n"
                 :: "r"(dst), "l"(src));
}
#define CP_COMMIT() asm volatile("cp.async.commit_group;\n" ::: "memory")
#define CP_WAIT(n)  asm volatile("cp.async.wait_group %0;\n" :: "n"(n) : "memory")

__device__ __forceinline__ void ldm_x4(uint32_t r[4], uint32_t addr) {
    asm volatile("ldmatrix.sync.aligned.m8n8.x4.shared.b16 {%0,%1,%2,%3}, [%4];"
                 : "=r"(r[0]), "=r"(r[1]), "=r"(r[2]), "=r"(r[3]) : "r"(addr));
}
__device__ __forceinline__ void ldm_x4_t(uint32_t r[4], uint32_t addr) {
    asm volatile("ldmatrix.sync.aligned.m8n8.x4.trans.shared.b16 {%0,%1,%2,%3}, [%4];"
                 : "=r"(r[0]), "=r"(r[1]), "=r"(r[2]), "=r"(r[3]) : "r"(addr));
}

__device__ __forceinline__ void mma16816h(float c[4], const uint32_t a[4],
                                          const uint32_t b[2]) {
    asm volatile(
        "mma.sync.aligned.m16n8k16.row.col.f32.f16.f16.f32 "
        "{%0,%1,%2,%3}, {%4,%5,%6,%7}, {%8,%9}, {%0,%1,%2,%3};"
        : "+f"(c[0]), "+f"(c[1]), "+f"(c[2]), "+f"(c[3])
        : "r"(a[0]), "r"(a[1]), "r"(a[2]), "r"(a[3]), "r"(b[0]), "r"(b[1]));
}

__device__ __forceinline__ float ex2(float x) {
    float r; asm("ex2.approx.f32 %0, %1;" : "=f"(r) : "f"(x)); return r;
}
__device__ __forceinline__ uint32_t pack_f16x2(float lo, float hi) {
    uint32_t d;
    asm("cvt.rn.f16x2.f32 %0, %1, %2;" : "=r"(d) : "f"(hi), "f"(lo));
    return d;
}

// ------------------------- conversion kernels ------------------------------
__global__ void convert_f16(const float* __restrict__ src,
                            __half* __restrict__ dst, int n4) {
    int i = blockIdx.x * blockDim.x + threadIdx.x;
    if (i >= n4) return;
    float4 v = ((const float4*)src)[i];
    ((__half2*)dst)[i * 2 + 0] = __floats2half2_rn(v.x, v.y);
    ((__half2*)dst)[i * 2 + 1] = __floats2half2_rn(v.z, v.w);
}

// src[K,N] fp32 -> out[N,K] fp16; cols < scale_cols scaled by `scale`
__global__ void transpose_f16(const float* __restrict__ src,
                              __half* __restrict__ dst,
                              int K, int N, int scale_cols, float scale) {
    __shared__ float tile[32][33];
    const int n0 = blockIdx.x * 32, k0 = blockIdx.y * 32;
    const int tx = threadIdx.x, ty = threadIdx.y;
    #pragma unroll
    for (int j = 0; j < 4; j++) {
        int r = ty + j * 8;
        float v = src[(size_t)(k0 + r) * N + n0 + tx];
        if (n0 + tx < scale_cols) v *= scale;
        tile[r][tx] = v;
    }
    __syncthreads();
    #pragma unroll
    for (int j = 0; j < 4; j++) {
        int b = ty + j * 8;
        dst[(size_t)(n0 + b) * K + k0 + tx] = __float2half_rn(tile[tx][b]);
    }
}

// ------------------------- fp16 multistage GEMM -----------------------------
constexpr int ROWB = 80;
constexpr int TILEB = 128 * ROWB;
constexpr int BUF16 = 2 * TILEB;              // A + B per stage
constexpr int SMEM_G16_BYTES = 4 * BUF16;     // 4 stages = 81920

__device__ __forceinline__ void load_tile_p(uint32_t dst, const void* src0,
                                            int row0, int k0, int K, int t) {
    const char* sp = (const char*)src0 + ((size_t)row0 * K + k0) * 2;
    const size_t rs = (size_t)K * 2;
    #pragma unroll
    for (int i = 0; i < 2; i++) {
        int s = i * 256 + t;
        int row = s >> 2, seg = (s & 3) * 16;
        cp_async16(dst + row * ROWB + seg, sp + (size_t)row * rs + seg);
    }
}

// MODE 0: write fp16 C. MODE 1: write fp32 C + bias.
template <int MODE>
__global__ __launch_bounds__(256) void gemm_f16(
    const __half* __restrict__ A, const __half* __restrict__ B,
    const float* __restrict__ bias,
    __half* __restrict__ Ch, float* __restrict__ Cf, int N, int K)
{
    extern __shared__ char smem[];
    const uint32_t sb = smem_u32(smem);
    const int t = threadIdx.x, wid = t >> 5, lane = t & 31;
    const int warp_m = wid & 3, warp_n = wid >> 2;

    const int rowA = blockIdx.y * 128, rowB = blockIdx.x * 128;
    const int nch = K / 32;

    float acc[2][8][4];
    #pragma unroll
    for (int mt = 0; mt < 2; mt++)
        #pragma unroll
        for (int nt = 0; nt < 8; nt++)
            #pragma unroll
            for (int j = 0; j < 4; j++) acc[mt][nt][j] = 0.f;

    // prologue: fill stages 0..2
    #pragma unroll
    for (int c = 0; c < 3; c++) {
        uint32_t bb = sb + c * BUF16;
        load_tile_p(bb, A, rowA, c * 32, K, t);
        load_tile_p(bb + TILEB, B, rowB, c * 32, K, t);
        CP_COMMIT();
    }

    const int lrow = lane & 15;
    const uint32_t lcol = (lane >> 4) << 4;

    for (int c = 0; c < nch; c++) {
        CP_WAIT(2);                 // stage c's group complete
        __syncthreads();            // all warps done with stage c-1 (= buffer (c+3)&3)
        if (c + 3 < nch) {
            uint32_t nb = sb + ((c + 3) & 3) * BUF16;
            load_tile_p(nb, A, rowA, (c + 3) * 32, K, t);
            load_tile_p(nb + TILEB, B, rowB, (c + 3) * 32, K, t);
        }
        CP_COMMIT();                // unconditional: keeps group ledger aligned

        const uint32_t bb = sb + (c & 3) * BUF16;
        const uint32_t sA = bb, sB = bb + TILEB;

        #pragma unroll
        for (int kk = 0; kk < 2; kk++) {
            const uint32_t coff = kk * 32 + lcol;
            uint32_t a4[2][4];
            #pragma unroll
            for (int mt = 0; mt < 2; mt++)
                ldm_x4(a4[mt], sA + (warp_m * 32 + mt * 16 + lrow) * ROWB + coff);
            uint32_t b2[8][2];
            #pragma unroll
            for (int g = 0; g < 4; g++) {
                uint32_t r[4];
                ldm_x4(r, sB + (warp_n * 64 + g * 16 + lrow) * ROWB + coff);
                b2[2 * g][0] = r[0]; b2[2 * g][1] = r[2];
                b2[2 * g + 1][0] = r[1]; b2[2 * g + 1][1] = r[3];
            }
            #pragma unroll
            for (int mt = 0; mt < 2; mt++)
                #pragma unroll
                for (int nt = 0; nt < 8; nt++)
                    mma16816h(acc[mt][nt], a4[mt], b2[nt]);
        }
    }

    #pragma unroll
    for (int mt = 0; mt < 2; mt++) {
        const int r0 = blockIdx.y * 128 + warp_m * 32 + mt * 16 + (lane >> 2);
        #pragma unroll
        for (int nt = 0; nt < 8; nt++) {
            const int col = blockIdx.x * 128 + warp_n * 64 + nt * 8 + (lane & 3) * 2;
            if (MODE == 1) {
                const float2 b2 = *(const float2*)(bias + col);
                *(float2*)(Cf + (size_t)r0 * N + col) =
                    make_float2(acc[mt][nt][0] + b2.x, acc[mt][nt][1] + b2.y);
                *(float2*)(Cf + (size_t)(r0 + 8) * N + col) =
                    make_float2(acc[mt][nt][2] + b2.x, acc[mt][nt][3] + b2.y);
            } else {
                #pragma unroll
                for (int hrow = 0; hrow < 2; hrow++) {
                    const __half2 hv = __floats2half2_rn(acc[mt][nt][hrow * 2],
                                                         acc[mt][nt][hrow * 2 + 1]);
                    *(__half2*)(Ch + (size_t)(r0 + 8 * hrow) * N + col) = hv;
                }
            }
        }
    }
}

// ------------------------- fp16 multistage flash attention ------------------
constexpr int AROWB = 144;
constexpr int QTILEB = 128 * AROWB;
constexpr int KTILEB = 64 * AROWB;
constexpr int KVBUF = 2 * KTILEB;                    // K + V per stage
constexpr int SMEM_ATT_BYTES = QTILEB + 4 * KVBUF;   // 92160

__device__ __forceinline__ void att_load(uint32_t dst, const __half* src,
                                         int rows256, int t) {
    #pragma unroll
    for (int i = 0; i < 4; i++) {
        if (i >= rows256) break;
        int s = i * 256 + t;
        int r = s >> 3, seg = (s & 7) * 16;
        cp_async16(dst + r * AROWB + seg, (const char*)src + (size_t)r * 6144 + seg);
    }
}

__global__ __launch_bounds__(256) void attn_mma(
    const __half* __restrict__ qkv, __half* __restrict__ att)
{
    extern __shared__ char smem[];
    const uint32_t sb = smem_u32(smem);
    const int t = threadIdx.x, wid = t >> 5, lane = t & 31;
    const int bh_ = blockIdx.y, b = bh_ >> 4, h = bh_ & 15;
    const int q0 = blockIdx.x * 128;
    const size_t rb = (size_t)b * 2048;

    const uint32_t QT = sb;
    const uint32_t KV0 = sb + QTILEB;
    const __half* k_b = qkv + rb * 3072 + 1024 + h * 64;
    const __half* v_b = qkv + rb * 3072 + 2048 + h * 64;

    // Q joins stage-0's commit group; stages 0..2 prefilled
    att_load(QT, qkv + (rb + q0) * 3072 + h * 64, 4, t);
    #pragma unroll
    for (int c = 0; c < 3; c++) {
        const uint32_t kb = KV0 + c * KVBUF;
        att_load(kb, k_b + (size_t)(c * 64) * 3072, 2, t);
        att_load(kb + KTILEB, v_b + (size_t)(c * 64) * 3072, 2, t);
        CP_COMMIT();
    }

    float oacc[8][4];
    #pragma unroll
    for (int nd = 0; nd < 8; nd++)
        #pragma unroll
        for (int j = 0; j < 4; j++) oacc[nd][j] = 0.f;
    float m0 = -1e30f, m1 = -1e30f, l0 = 0.f, l1 = 0.f;

    const int lrow = lane & 15;
    const uint32_t lcol = (lane >> 4) << 4;

    for (int c = 0; c < 32; c++) {
        CP_WAIT(2);
        __syncthreads();
        if (c + 3 < 32) {
            const uint32_t nb = KV0 + ((c + 3) & 3) * KVBUF;
            const size_t j0 = (size_t)((c + 3) * 64) * 3072;
            att_load(nb, k_b + j0, 2, t);
            att_load(nb + KTILEB, v_b + j0, 2, t);
        }
        CP_COMMIT();

        const uint32_t kb = KV0 + (c & 3) * KVBUF;
        const uint32_t sK = kb, sV = kb + KTILEB;

        float sacc[8][4];
        #pragma unroll
        for (int nt = 0; nt < 8; nt++)
            #pragma unroll
            for (int j = 0; j < 4; j++) sacc[nt][j] = 0.f;

        #pragma unroll
        for (int kt = 0; kt < 4; kt++) {
            const uint32_t coff = kt * 32 + lcol;
            uint32_t q4[4];
            ldm_x4(q4, QT + (wid * 16 + lrow) * AROWB + coff);
            uint32_t bk[8][2];
            #pragma unroll
            for (int g = 0; g < 4; g++) {
                uint32_t r[4];
                ldm_x4(r, sK + (g * 16 + lrow) * AROWB + coff);
                bk[2 * g][0] = r[0]; bk[2 * g][1] = r[2];
                bk[2 * g + 1][0] = r[1]; bk[2 * g + 1][1] = r[3];
            }
            #pragma unroll
            for (int nt = 0; nt < 8; nt++)
                mma16816h(sacc[nt], q4, bk[nt]);
        }

        float tm0 = -1e30f, tm1 = -1e30f;
        #pragma unroll
        for (int nt = 0; nt < 8; nt++) {
            tm0 = fmaxf(tm0, fmaxf(sacc[nt][0], sacc[nt][1]));
            tm1 = fmaxf(tm1, fmaxf(sacc[nt][2], sacc[nt][3]));
        }
        tm0 = fmaxf(tm0, __shfl_xor_sync(0xffffffffu, tm0, 1));
        tm0 = fmaxf(tm0, __shfl_xor_sync(0xffffffffu, tm0, 2));
        tm1 = fmaxf(tm1, __shfl_xor_sync(0xffffffffu, tm1, 1));
        tm1 = fmaxf(tm1, __shfl_xor_sync(0xffffffffu, tm1, 2));
        const float nm0 = fmaxf(m0, tm0), nm1 = fmaxf(m1, tm1);
        const float cr0 = ex2(m0 - nm0), cr1 = ex2(m1 - nm1);
        m0 = nm0; m1 = nm1;
        l0 *= cr0; l1 *= cr1;
        #pragma unroll
        for (int nd = 0; nd < 8; nd++) {
            oacc[nd][0] *= cr0; oacc[nd][1] *= cr0;
            oacc[nd][2] *= cr1; oacc[nd][3] *= cr1;
        }
        float rs0 = 0.f, rs1 = 0.f;
        #pragma unroll
        for (int nt = 0; nt < 8; nt++) {
            float p0 = ex2(sacc[nt][0] - m0), p1 = ex2(sacc[nt][1] - m0);
            float p2 = ex2(sacc[nt][2] - m1), p3 = ex2(sacc[nt][3] - m1);
            sacc[nt][0] = p0; sacc[nt][1] = p1; sacc[nt][2] = p2; sacc[nt][3] = p3;
            rs0 += p0 + p1; rs1 += p2 + p3;
        }
        rs0 += __shfl_xor_sync(0xffffffffu, rs0, 1);
        rs0 += __shfl_xor_sync(0xffffffffu, rs0, 2);
        rs1 += __shfl_xor_sync(0xffffffffu, rs1, 1);
        rs1 += __shfl_xor_sync(0xffffffffu, rs1, 2);
        l0 += rs0; l1 += rs1;

        #pragma unroll
        for (int kt = 0; kt < 4; kt++) {
            uint32_t ap[4];
            #pragma unroll
            for (int half = 0; half < 2; half++) {
                const float* sp = sacc[2 * kt + half];
                ap[half * 2 + 0] = pack_f16x2(sp[0], sp[1]);
                ap[half * 2 + 1] = pack_f16x2(sp[2], sp[3]);
            }
            uint32_t bv[8][2];
            #pragma unroll
            for (int nd2 = 0; nd2 < 4; nd2++) {
                uint32_t r[4];
                ldm_x4_t(r, sV + (kt * 16 + lrow) * AROWB + nd2 * 32 + lcol);
                bv[2 * nd2][0] = r[0]; bv[2 * nd2][1] = r[1];
                bv[2 * nd2 + 1][0] = r[2]; bv[2 * nd2 + 1][1] = r[3];
            }
            #pragma unroll
            for (int nd = 0; nd < 8; nd++)
                mma16816h(oacc[nd], ap, bv[nd]);
        }
    }

    // epilogue: normalize + fp16 write
    const float inv0 = 1.f / l0, inv1 = 1.f / l1;
    const int r0 = q0 + wid * 16 + (lane >> 2);
    #pragma unroll
    for (int nd = 0; nd < 8; nd++) {
        const int col = h * 64 + nd * 8 + (lane & 3) * 2;
        #pragma unroll
        for (int hrow = 0; hrow < 2; hrow++) {
            const float inv = hrow ? inv1 : inv0;
            const __half2 hv = __floats2half2_rn(oacc[nd][hrow * 2] * inv,
                                                 oacc[nd][hrow * 2 + 1] * inv);
            *(__half2*)(att + (rb + r0 + 8 * hrow) * 1024 + col) = hv;
        }
    }
}

// ------------------------- launch ------------------------------------------
extern "C" void kernel_launch(void* const* d_in, const int* in_sizes, int n_in,
                              void* d_out, int out_size)
{
    const float* x     = (const float*)d_in[0];
    const float* w_qkv = (const float*)d_in[1];
    const float* w_out = (const float*)d_in[2];
    const float* b_out = (const float*)d_in[3];
    float* out = (float*)d_out;

    __half *x16, *wq16, *wo16, *qkv16, *att16;
    cudaGetSymbolAddress((void**)&x16, g_x16);
    cudaGetSymbolAddress((void**)&wq16, g_wqkvt16);
    cudaGetSymbolAddress((void**)&wo16, g_woutt16);
    cudaGetSymbolAddress((void**)&qkv16, g_qkv16);
    cudaGetSymbolAddress((void**)&att16, g_att16);

    cudaFuncSetAttribute(gemm_f16<0>, cudaFuncAttributeMaxDynamicSharedMemorySize,
                         SMEM_G16_BYTES);
    cudaFuncSetAttribute(gemm_f16<1>, cudaFuncAttributeMaxDynamicSharedMemorySize,
                         SMEM_G16_BYTES);
    cudaFuncSetAttribute(attn_mma, cudaFuncAttributeMaxDynamicSharedMemorySize,
                         SMEM_ATT_BYTES);

    // prep
    convert_f16<<<(8192 * 1024 / 4 + 255) / 256, 256>>>(x, x16, 8192 * 1024 / 4);
    transpose_f16<<<dim3(3072 / 32, 1024 / 32), dim3(32, 8)>>>(
        w_qkv, wq16, 1024, 3072, 1024, ATT_SCALE * LOG2E);
    transpose_f16<<<dim3(1024 / 32, 1024 / 32), dim3(32, 8)>>>(
        w_out, wo16, 1024, 1024, 0, 1.f);

    // stage 1: qkv = x @ w_qkv (fp16)
    gemm_f16<0><<<dim3(3072 / 128, 8192 / 128), 256, SMEM_G16_BYTES>>>(
        x16, wq16, nullptr, qkv16, nullptr, 3072, 1024);

    // stage 2: flash attention (fp16), writes fp16 att
    attn_mma<<<dim3(2048 / 128, 64), 256, SMEM_ATT_BYTES>>>(qkv16, att16);

    // stage 3: out = att @ w_out + b (fp16, fp32 out)
    gemm_f16<1><<<dim3(1024 / 128, 8192 / 128), 256, SMEM_G16_BYTES>>>(
        att16, wo16, b_out, nullptr, out, 1024, 1024);
}